// round 4
// baseline (speedup 1.0000x reference)
#include <cuda_runtime.h>
#include <cuda_bf16.h>
#include <math.h>
#include <stdint.h>

#define B 256
#define DIM 1024
#define H 8
#define D 128
#define P 2048
#define HD 1024
#define KER 4

typedef __nv_bfloat16 bf16;

// ---------------- static scratch ----------------
#define WTOT 14680064
__device__ bf16 g_wh[WTOT];
__device__ bf16 g_wl[WTOT];
__device__ bf16 g_xnh[B * DIM], g_xnl[B * DIM];
__device__ bf16 g_xth[B * P],   g_xtl[B * P];
__device__ bf16 g_xch[B * P],   g_xcl[B * P];
__device__ bf16 g_yh[B * HD],   g_yl[B * HD];
__device__ float g_rt[B * HD];
__device__ float g_q[B * HD];
__device__ float g_k[B * HD];
__device__ float g_v[B * HD];
__device__ float g_o[B * HD];
__device__ float g_sk[B * HD];
__device__ float g_ie[B * H];
__device__ float g_fe[B * H];

// weight plane offsets (elements)
#define OF_WUL 0
#define OF_WUR 2097152
#define OF_WQ  3145728
#define OF_WK  5242880
#define OF_WV  7340032
#define OF_WO  9437184
#define OF_WSK 11534336
#define OF_WD  13631488

__device__ __forceinline__ uint32_t smem_u32(const void* p) {
    uint32_t a;
    asm("{ .reg .u64 t; cvta.to.shared.u64 t, %1; cvt.u32.u64 %0, t; }" : "=r"(a) : "l"(p));
    return a;
}
// split two fp32 into packed bf16x2 hi + lo (lo = exact residual rounded)
__device__ __forceinline__ void split2(float a, float b, uint32_t& hi, uint32_t& lo) {
    asm("cvt.rn.bf16x2.f32 %0, %1, %2;" : "=r"(hi) : "f"(b), "f"(a));
    float ha = __uint_as_float(hi << 16);
    float hb = __uint_as_float(hi & 0xffff0000u);
    asm("cvt.rn.bf16x2.f32 %0, %1, %2;" : "=r"(lo) : "f"(b - hb), "f"(a - ha));
}

#define LDM4(r, a) \
    asm volatile("ldmatrix.sync.aligned.m8n8.x4.shared.b16 {%0,%1,%2,%3}, [%4];" \
        : "=r"((r)[0]), "=r"((r)[1]), "=r"((r)[2]), "=r"((r)[3]) : "r"(a))
#define MMA(d, a, b0, b1) \
    asm volatile("mma.sync.aligned.m16n8k16.row.col.f32.bf16.bf16.f32 " \
        "{%0,%1,%2,%3}, {%4,%5,%6,%7}, {%8,%9}, {%0,%1,%2,%3};" \
        : "+f"((d)[0]), "+f"((d)[1]), "+f"((d)[2]), "+f"((d)[3]) \
        : "r"((a)[0]), "r"((a)[1]), "r"((a)[2]), "r"((a)[3]), "r"(b0), "r"(b1))

// ================= weight split kernel =================
struct WEnt { const float* src; int off; int n4; };
struct WArgs { WEnt w[8]; bf16* hi; bf16* lo; };

__global__ void wsplit_kernel(WArgs a) {
    WEnt e = a.w[blockIdx.z];
    bf16* hi = a.hi + e.off;
    bf16* lo = a.lo + e.off;
    int i = blockIdx.x * 256 + threadIdx.x;
    int stride = gridDim.x * 256;
    for (; i < e.n4; i += stride) {
        float4 v = ((const float4*)e.src)[i];
        uint32_t h01, l01, h23, l23;
        split2(v.x, v.y, h01, l01);
        split2(v.z, v.w, h23, l23);
        *(uint2*)(hi + i * 4) = make_uint2(h01, h23);
        *(uint2*)(lo + i * 4) = make_uint2(l01, l23);
    }
}

// ================= layernorm (writes bf16 hi/lo planes) =================
__global__ void ln_kernel(const float* __restrict__ x, const float* __restrict__ g,
                          const float* __restrict__ bta, bf16* __restrict__ oh,
                          bf16* __restrict__ ol) {
    int row = blockIdx.x;
    int tid = threadIdx.x;
    const float4* xr = (const float4*)(x + (size_t)row * DIM);
    float4 v = xr[tid];
    float s  = v.x + v.y + v.z + v.w;
    float ss = v.x * v.x + v.y * v.y + v.z * v.z + v.w * v.w;
    __shared__ float shs[8], shss[8];
    __shared__ float mu_s, rstd_s;
    #pragma unroll
    for (int o = 16; o; o >>= 1) {
        s  += __shfl_down_sync(0xffffffffu, s, o);
        ss += __shfl_down_sync(0xffffffffu, ss, o);
    }
    int w = tid >> 5, lane = tid & 31;
    if (lane == 0) { shs[w] = s; shss[w] = ss; }
    __syncthreads();
    if (tid == 0) {
        float ts = 0.f, tss = 0.f;
        #pragma unroll
        for (int i = 0; i < 8; i++) { ts += shs[i]; tss += shss[i]; }
        float mu = ts * (1.f / DIM);
        float var = tss * (1.f / DIM) - mu * mu;
        mu_s = mu;
        rstd_s = rsqrtf(var + 1e-5f);
    }
    __syncthreads();
    float mu = mu_s, rs = rstd_s;
    float4 g4 = ((const float4*)g)[tid];
    float4 b4 = ((const float4*)bta)[tid];
    float r0 = (v.x - mu) * rs * g4.x + b4.x;
    float r1 = (v.y - mu) * rs * g4.y + b4.y;
    float r2 = (v.z - mu) * rs * g4.z + b4.z;
    float r3 = (v.w - mu) * rs * g4.w + b4.w;
    uint32_t h01, l01, h23, l23;
    split2(r0, r1, h01, l01);
    split2(r2, r3, h23, l23);
    *(uint2*)(oh + (size_t)row * DIM + tid * 4) = make_uint2(h01, h23);
    *(uint2*)(ol + (size_t)row * DIM + tid * 4) = make_uint2(l01, l23);
}

// ================= async tensor-core GEMM NT =================
// C[M,N] = (Ah+Al)[M,K] @ (Wh+Wl)[N,K]^T  (3-term bf16 split, fp32 accum)
struct GemmDesc {
    const bf16 *Ah, *Al, *Wh, *Wl;
    const float* bias;   // nullable
    const float* res;    // nullable (mode 0 only)
    float* C;            // mode 0
    bf16 *Ch, *Cl;       // mode 1
    int N, K, mode, epi; // mode: 0 fp32 out, 1 bf16 plane out; epi 1 = sigmoid
};
struct GemmArgs { GemmDesc d[5]; };

#define MATP 10240          // 128 rows x 80B padded
#define STG  40960          // 4 matrices per stage
#define GEMM_SMEM (3 * STG) // 122880

__device__ __forceinline__ void issue_stage(uint32_t sdst,
        const bf16* aH, const bf16* aL, const bf16* wH, const bf16* wL,
        int k0, int K, int tid, bool valid) {
    if (valid) {
        const bf16* bases[4] = {aH, aL, wH, wL};
        int r0 = tid >> 2, c = tid & 3;
        #pragma unroll
        for (int j = 0; j < 8; j++) {
            int mat = j >> 1;
            int r = r0 + (j & 1) * 64;
            const char* src = (const char*)(bases[mat] + (size_t)r * K + k0) + c * 16;
            uint32_t dst = sdst + mat * MATP + r * 80 + c * 16;
            asm volatile("cp.async.cg.shared.global [%0], [%1], 16;" :: "r"(dst), "l"(src) : "memory");
        }
    }
    asm volatile("cp.async.commit_group;" ::: "memory");
}

__global__ __launch_bounds__(256, 1) void gemm_async(GemmArgs args) {
    extern __shared__ char smem[];
    const GemmDesc dd = args.d[blockIdx.z];
    const int N = dd.N, K = dd.K;
    const int bn0 = blockIdx.x * 128;
    const int bm0 = blockIdx.y * 128;
    if (bn0 >= N) return;

    const uint32_t sbase = smem_u32(smem);
    const int tid = threadIdx.x, wid = tid >> 5, lane = tid & 31;
    const int m0 = (wid & 1) * 64, n0 = (wid >> 1) * 32;
    const int grp = lane >> 3, lrow = lane & 7;

    const bf16* aH = dd.Ah + (size_t)bm0 * K;
    const bf16* aL = dd.Al + (size_t)bm0 * K;
    const bf16* wH = dd.Wh + (size_t)bn0 * K;
    const bf16* wL = dd.Wl + (size_t)bn0 * K;

    uint32_t aoff[4], boff[2];
    #pragma unroll
    for (int mi = 0; mi < 4; mi++)
        aoff[mi] = (uint32_t)((m0 + mi * 16 + (grp & 1) * 8 + lrow) * 80 + (grp >> 1) * 16);
    #pragma unroll
    for (int bi = 0; bi < 2; bi++)
        boff[bi] = (uint32_t)((n0 + bi * 16 + (grp >> 1) * 8 + lrow) * 80 + (grp & 1) * 16);

    float acc[4][4][4];
    #pragma unroll
    for (int mi = 0; mi < 4; mi++)
        #pragma unroll
        for (int ni = 0; ni < 4; ni++)
            acc[mi][ni][0] = acc[mi][ni][1] = acc[mi][ni][2] = acc[mi][ni][3] = 0.f;

    const int nk = K >> 5;
    issue_stage(sbase,       aH, aL, wH, wL, 0,  K, tid, true);
    issue_stage(sbase + STG, aH, aL, wH, wL, 32, K, tid, 1 < nk);

    for (int it = 0; it < nk; it++) {
        asm volatile("cp.async.wait_group 1;" ::: "memory");
        __syncthreads();
        const int nxt = it + 2;
        issue_stage(sbase + (nxt % 3) * STG, aH, aL, wH, wL, nxt << 5, K, tid, nxt < nk);

        const uint32_t sA  = sbase + (it % 3) * STG;
        const uint32_t sAl = sA + MATP, sWh = sA + 2 * MATP, sWl = sA + 3 * MATP;
        #pragma unroll
        for (int ks = 0; ks < 2; ks++) {
            const uint32_t kb = ks * 32;
            uint32_t Ah[4][4], Al[4][4], Bh[4][2], Bl[4][2];
            #pragma unroll
            for (int mi = 0; mi < 4; mi++) {
                LDM4(Ah[mi], sA  + aoff[mi] + kb);
                LDM4(Al[mi], sAl + aoff[mi] + kb);
            }
            #pragma unroll
            for (int bi = 0; bi < 2; bi++) {
                uint32_t t[4];
                LDM4(t, sWh + boff[bi] + kb);
                Bh[2 * bi][0] = t[0]; Bh[2 * bi][1] = t[1];
                Bh[2 * bi + 1][0] = t[2]; Bh[2 * bi + 1][1] = t[3];
                LDM4(t, sWl + boff[bi] + kb);
                Bl[2 * bi][0] = t[0]; Bl[2 * bi][1] = t[1];
                Bl[2 * bi + 1][0] = t[2]; Bl[2 * bi + 1][1] = t[3];
            }
            #pragma unroll
            for (int mi = 0; mi < 4; mi++)
                #pragma unroll
                for (int ni = 0; ni < 4; ni++) {
                    MMA(acc[mi][ni], Ah[mi], Bh[ni][0], Bh[ni][1]);
                    MMA(acc[mi][ni], Ah[mi], Bl[ni][0], Bl[ni][1]);
                    MMA(acc[mi][ni], Al[mi], Bh[ni][0], Bh[ni][1]);
                }
        }
    }
    asm volatile("cp.async.wait_all;" ::: "memory");

    // epilogue
    const int qrow = lane >> 2, qcol = (lane & 3) * 2;
    #pragma unroll
    for (int ni = 0; ni < 4; ni++) {
        const int c = bn0 + n0 + ni * 8 + qcol;
        float2 bb = make_float2(0.f, 0.f);
        if (dd.bias) bb = *(const float2*)(dd.bias + c);
        #pragma unroll
        for (int mi = 0; mi < 4; mi++) {
            const int r = bm0 + m0 + mi * 16 + qrow;
            float v0 = acc[mi][ni][0] + bb.x;
            float v1 = acc[mi][ni][1] + bb.y;
            float v2 = acc[mi][ni][2] + bb.x;
            float v3 = acc[mi][ni][3] + bb.y;
            if (dd.epi == 1) {
                v0 = 1.f / (1.f + expf(-v0)); v1 = 1.f / (1.f + expf(-v1));
                v2 = 1.f / (1.f + expf(-v2)); v3 = 1.f / (1.f + expf(-v3));
            }
            if (dd.mode == 0) {
                if (dd.res) {
                    float2 r0 = *(const float2*)(dd.res + (size_t)r * N + c);
                    float2 r1 = *(const float2*)(dd.res + (size_t)(r + 8) * N + c);
                    v0 += r0.x; v1 += r0.y; v2 += r1.x; v3 += r1.y;
                }
                *(float2*)(dd.C + (size_t)r * N + c) = make_float2(v0, v1);
                *(float2*)(dd.C + (size_t)(r + 8) * N + c) = make_float2(v2, v3);
            } else {
                uint32_t hh, ll;
                split2(v0, v1, hh, ll);
                *(uint32_t*)(dd.Ch + (size_t)r * N + c) = hh;
                *(uint32_t*)(dd.Cl + (size_t)r * N + c) = ll;
                split2(v2, v3, hh, ll);
                *(uint32_t*)(dd.Ch + (size_t)(r + 8) * N + c) = hh;
                *(uint32_t*)(dd.Cl + (size_t)(r + 8) * N + c) = ll;
            }
        }
    }
}

// ================= causal conv (k=4) + silu (planes in/out) =================
__global__ void conv_silu_kernel(const bf16* __restrict__ xth, const bf16* __restrict__ xtl,
                                 const float* __restrict__ w, const float* __restrict__ cb,
                                 bf16* __restrict__ xch, bf16* __restrict__ xcl) {
    int b = blockIdx.y;
    int p = blockIdx.x * 256 + threadIdx.x;
    size_t base = (size_t)b * P;
    float acc = cb[0];
    #pragma unroll
    for (int j = 0; j < KER; j++) {
        int idx = p - (KER - 1) + j;
        if (idx >= 0) {
            float x = __bfloat162float(xth[base + idx]) + __bfloat162float(xtl[base + idx]);
            acc += w[j] * x;
        }
    }
    float s = acc / (1.f + expf(-acc));
    bf16 hi = __float2bfloat16(s);
    xch[base + p] = hi;
    xcl[base + p] = __float2bfloat16(s - __bfloat162float(hi));
}

// ================= i/f gates: one block per (b,h) =================
__global__ __launch_bounds__(128) void if_kernel(
        const bf16* __restrict__ xch, const bf16* __restrict__ xcl,
        const float* __restrict__ Wi, const float* __restrict__ bi,
        const float* __restrict__ Wf, const float* __restrict__ bfb,
        const float* __restrict__ m_tm1, float* __restrict__ m_out,
        float* __restrict__ ie, float* __restrict__ fe) {
    int bh = blockIdx.x;
    int b = bh >> 3, h = bh & 7;
    int tid = threadIdx.x;
    const __nv_bfloat162* xh = (const __nv_bfloat162*)(xch + (size_t)b * P);
    const __nv_bfloat162* xl = (const __nv_bfloat162*)(xcl + (size_t)b * P);
    const float* wi = Wi + (size_t)h * P;
    const float* wf = Wf + (size_t)h * P;
    float ai = 0.f, af = 0.f;
    for (int k = tid * 4; k < P; k += 512) {
        __nv_bfloat162 h0 = xh[k >> 1], h1 = xh[(k >> 1) + 1];
        __nv_bfloat162 l0 = xl[k >> 1], l1 = xl[(k >> 1) + 1];
        float x0 = __bfloat162float(h0.x) + __bfloat162float(l0.x);
        float x1 = __bfloat162float(h0.y) + __bfloat162float(l0.y);
        float x2 = __bfloat162float(h1.x) + __bfloat162float(l1.x);
        float x3 = __bfloat162float(h1.y) + __bfloat162float(l1.y);
        float4 wiv = *(const float4*)(wi + k);
        float4 wfv = *(const float4*)(wf + k);
        ai += x0 * wiv.x + x1 * wiv.y + x2 * wiv.z + x3 * wiv.w;
        af += x0 * wfv.x + x1 * wfv.y + x2 * wfv.z + x3 * wfv.w;
    }
    __shared__ float si[4], sf[4];
    #pragma unroll
    for (int o = 16; o; o >>= 1) {
        ai += __shfl_down_sync(0xffffffffu, ai, o);
        af += __shfl_down_sync(0xffffffffu, af, o);
    }
    int w = tid >> 5, lane = tid & 31;
    if (lane == 0) { si[w] = ai; sf[w] = af; }
    __syncthreads();
    if (tid == 0) {
        float i_t = si[0] + si[1] + si[2] + si[3] + bi[h];
        float f_t = sf[0] + sf[1] + sf[2] + sf[3] + bfb[h];
        float mp = m_tm1[bh];
        float m = fmaxf(f_t + mp, i_t);
        m_out[bh] = m;
        ie[bh] = expf(i_t - m);
        fe[bh] = expf(f_t - m + mp);
    }
}

// ================= fused state update + readout + groupnorm + gating ========
__global__ __launch_bounds__(128) void state_kernel(
    const float* __restrict__ c_tm1, const float* __restrict__ n_tm1,
    const float* __restrict__ q, const float* __restrict__ k, const float* __restrict__ v,
    const float* __restrict__ o, const float* __restrict__ ie_, const float* __restrict__ fe_,
    const float* __restrict__ skip, const float* __restrict__ r,
    const float* __restrict__ gn_g, const float* __restrict__ gn_b,
    float* __restrict__ c_out, float* __restrict__ n_out,
    bf16* __restrict__ yh, bf16* __restrict__ yl) {
    int bh = blockIdx.x;
    int b = bh >> 3, h = bh & 7;
    __shared__ float qs[D], ks[D], vs[D], hnum[D];
    __shared__ float red[4], rs1[4], rs2[4];
    int tid = threadIdx.x;
    int base = b * HD + h * D;
    qs[tid] = q[base + tid];
    ks[tid] = k[base + tid] * 0.08838834764831845f;   // 1/sqrt(128)
    vs[tid] = v[base + tid];
    float ie = ie_[bh], fe = fe_[bh];
    __syncthreads();

    const float4* crow = (const float4*)(c_tm1 + (size_t)bh * D * D);
    float4* cout = (float4*)(c_out + (size_t)bh * D * D);
    int w = tid >> 5, lane = tid & 31;
    float4 k4 = ((const float4*)ks)[lane];
    float4 q4 = ((const float4*)qs)[lane];
    #pragma unroll 4
    for (int it = 0; it < 32; it++) {
        int d = it * 4 + w;
        float4 c4 = crow[d * 32 + lane];
        float ivd = ie * vs[d];
        float4 cn;
        cn.x = fe * c4.x + ivd * k4.x;
        cn.y = fe * c4.y + ivd * k4.y;
        cn.z = fe * c4.z + ivd * k4.z;
        cn.w = fe * c4.w + ivd * k4.w;
        cout[d * 32 + lane] = cn;
        float part = cn.x * q4.x + cn.y * q4.y + cn.z * q4.z + cn.w * q4.w;
        #pragma unroll
        for (int off = 16; off; off >>= 1) part += __shfl_down_sync(0xffffffffu, part, off);
        if (lane == 0) hnum[d] = part;
    }
    __syncthreads();

    int d = tid;
    float nv = fe * n_tm1[bh * D + d] + ie * ks[d];
    n_out[bh * D + d] = nv;
    float dn = nv * qs[d];
    #pragma unroll
    for (int off = 16; off; off >>= 1) dn += __shfl_down_sync(0xffffffffu, dn, off);
    if (lane == 0) red[w] = dn;
    __syncthreads();
    float denom = fmaxf(red[0] + red[1] + red[2] + red[3], 1.0f);
    float ht = o[base + d] * hnum[d] / denom;

    float s1 = ht, s2 = ht * ht;
    #pragma unroll
    for (int off = 16; off; off >>= 1) {
        s1 += __shfl_down_sync(0xffffffffu, s1, off);
        s2 += __shfl_down_sync(0xffffffffu, s2, off);
    }
    if (lane == 0) { rs1[w] = s1; rs2[w] = s2; }
    __syncthreads();
    float mu  = (rs1[0] + rs1[1] + rs1[2] + rs1[3]) * (1.f / D);
    float var = (rs2[0] + rs2[1] + rs2[2] + rs2[3]) * (1.f / D) - mu * mu;
    float rstd = rsqrtf(var + 1e-5f);
    float xn = (ht - mu) * rstd * gn_g[h * D + d] + gn_b[h * D + d];
    float rv = r[base + d];
    float yv = (xn + skip[base + d]) * (rv / (1.f + expf(-rv)));
    bf16 hi = __float2bfloat16(yv);
    yh[base + d] = hi;
    yl[base + d] = __float2bfloat16(yv - __bfloat162float(hi));
}

// ---------------------------------------------------------------------------
extern "C" void kernel_launch(void* const* d_in, const int* in_sizes, int n_in,
                              void* d_out, int out_size) {
    const float* seq    = (const float*)d_in[0];
    const float* c_tm1  = (const float*)d_in[1];
    const float* n_tm1  = (const float*)d_in[2];
    const float* m_tm1  = (const float*)d_in[3];
    const float* ln_g   = (const float*)d_in[4];
    const float* ln_b   = (const float*)d_in[5];
    const float* Wul    = (const float*)d_in[6];
    const float* bul    = (const float*)d_in[7];
    const float* Wur    = (const float*)d_in[8];
    const float* bur    = (const float*)d_in[9];
    const float* conv_w = (const float*)d_in[10];
    const float* conv_b = (const float*)d_in[11];
    const float* Wskip  = (const float*)d_in[12];
    const float* Wi     = (const float*)d_in[13];
    const float* bi     = (const float*)d_in[14];
    const float* Wf     = (const float*)d_in[15];
    const float* bf     = (const float*)d_in[16];
    const float* Wo     = (const float*)d_in[17];
    const float* bo     = (const float*)d_in[18];
    const float* Wq     = (const float*)d_in[19];
    const float* bq     = (const float*)d_in[20];
    const float* Wk     = (const float*)d_in[21];
    const float* bk     = (const float*)d_in[22];
    const float* Wv     = (const float*)d_in[23];
    const float* bv     = (const float*)d_in[24];
    const float* gn_g   = (const float*)d_in[25];
    const float* gn_b   = (const float*)d_in[26];
    const float* Wd     = (const float*)d_in[27];
    const float* bd     = (const float*)d_in[28];

    float* out   = (float*)d_out;
    float* c_out = out + (size_t)B * DIM;
    float* n_out = c_out + (size_t)B * H * D * D;
    float* m_out = n_out + (size_t)B * H * D;

    bf16 *wh, *wl, *xnh, *xnl, *xth, *xtl, *xch, *xcl, *yh, *yl;
    float *rt, *qq, *kk, *vv, *oo, *sk, *iee, *fee;
    cudaGetSymbolAddress((void**)&wh,  g_wh);
    cudaGetSymbolAddress((void**)&wl,  g_wl);
    cudaGetSymbolAddress((void**)&xnh, g_xnh);
    cudaGetSymbolAddress((void**)&xnl, g_xnl);
    cudaGetSymbolAddress((void**)&xth, g_xth);
    cudaGetSymbolAddress((void**)&xtl, g_xtl);
    cudaGetSymbolAddress((void**)&xch, g_xch);
    cudaGetSymbolAddress((void**)&xcl, g_xcl);
    cudaGetSymbolAddress((void**)&yh,  g_yh);
    cudaGetSymbolAddress((void**)&yl,  g_yl);
    cudaGetSymbolAddress((void**)&rt,  g_rt);
    cudaGetSymbolAddress((void**)&qq,  g_q);
    cudaGetSymbolAddress((void**)&kk,  g_k);
    cudaGetSymbolAddress((void**)&vv,  g_v);
    cudaGetSymbolAddress((void**)&oo,  g_o);
    cudaGetSymbolAddress((void**)&sk,  g_sk);
    cudaGetSymbolAddress((void**)&iee, g_ie);
    cudaGetSymbolAddress((void**)&fee, g_fe);

    cudaFuncSetAttribute(gemm_async, cudaFuncAttributeMaxDynamicSharedMemorySize, GEMM_SMEM);

    // 0. split all weights into bf16 hi/lo planes
    {
        WArgs a{};
        a.w[0] = {Wul,   OF_WUL, (P * DIM) / 4};
        a.w[1] = {Wur,   OF_WUR, (HD * DIM) / 4};
        a.w[2] = {Wq,    OF_WQ,  (HD * P) / 4};
        a.w[3] = {Wk,    OF_WK,  (HD * P) / 4};
        a.w[4] = {Wv,    OF_WV,  (HD * P) / 4};
        a.w[5] = {Wo,    OF_WO,  (HD * P) / 4};
        a.w[6] = {Wskip, OF_WSK, (HD * P) / 4};
        a.w[7] = {Wd,    OF_WD,  (DIM * HD) / 4};
        a.hi = wh; a.lo = wl;
        wsplit_kernel<<<dim3(512, 1, 8), 256>>>(a);
    }

    // 1. layernorm -> xn planes
    ln_kernel<<<B, 256>>>(seq, ln_g, ln_b, xnh, xnl);

    // 2+3. x_t (planes) and r_t (fp32)
    {
        GemmArgs a{};
        a.d[0] = {xnh, xnl, wh + OF_WUL, wl + OF_WUL, bul, nullptr, nullptr, xth, xtl, P,  DIM, 1, 0};
        a.d[1] = {xnh, xnl, wh + OF_WUR, wl + OF_WUR, bur, nullptr, rt, nullptr, nullptr, HD, DIM, 0, 0};
        gemm_async<<<dim3(P / 128, B / 128, 2), 256, GEMM_SMEM>>>(a);
    }

    // 4. conv + silu -> xc planes
    conv_silu_kernel<<<dim3(P / 256, B), 256>>>(xth, xtl, conv_w, conv_b, xch, xcl);

    // 5. gates
    if_kernel<<<B * H, 128>>>(xch, xcl, Wi, bi, Wf, bf, m_tm1, m_out, iee, fee);

    // 6. q,k,v,o,skip
    {
        GemmArgs a{};
        a.d[0] = {xch, xcl, wh + OF_WQ,  wl + OF_WQ,  bq, nullptr, qq, nullptr, nullptr, HD, P, 0, 0};
        a.d[1] = {xch, xcl, wh + OF_WK,  wl + OF_WK,  bk, nullptr, kk, nullptr, nullptr, HD, P, 0, 0};
        a.d[2] = {xth, xtl, wh + OF_WV,  wl + OF_WV,  bv, nullptr, vv, nullptr, nullptr, HD, P, 0, 0};
        a.d[3] = {xth, xtl, wh + OF_WO,  wl + OF_WO,  bo, nullptr, oo, nullptr, nullptr, HD, P, 0, 1};
        a.d[4] = {xch, xcl, wh + OF_WSK, wl + OF_WSK, nullptr, nullptr, sk, nullptr, nullptr, HD, P, 0, 0};
        gemm_async<<<dim3(HD / 128, B / 128, 5), 256, GEMM_SMEM>>>(a);
    }

    // 7. state update -> c_out, n_out, y planes
    state_kernel<<<B * H, 128>>>(c_tm1, n_tm1, qq, kk, vv, oo, iee, fee,
                                 sk, rt, gn_g, gn_b, c_out, n_out, yh, yl);

    // 8. out = y @ Wd^T + bd + seq
    {
        GemmArgs a{};
        a.d[0] = {yh, yl, wh + OF_WD, wl + OF_WD, bd, seq, out, nullptr, nullptr, DIM, HD, 0, 0};
        gemm_async<<<dim3(DIM / 128, B / 128, 1), 256, GEMM_SMEM>>>(a);
    }
}

// round 5
// speedup vs baseline: 1.3691x; 1.3691x over previous
#include <cuda_runtime.h>
#include <cuda_bf16.h>
#include <math.h>
#include <stdint.h>

#define B 256
#define DIM 1024
#define H 8
#define D 128
#define P 2048
#define HD 1024
#define KER 4

// ---------------- scratch (static device memory; no allocs) ----------------
__device__ float g_xn[B * DIM];
__device__ float g_xt[B * P];
__device__ float g_xc[B * P];
__device__ float g_rt[B * HD];
__device__ float g_q[B * HD];
__device__ float g_k[B * HD];
__device__ float g_v[B * HD];
__device__ float g_o[B * HD];
__device__ float g_sk[B * HD];
__device__ float g_ie[B * H];
__device__ float g_fe[B * H];
__device__ float g_y[B * HD];

__device__ __forceinline__ uint32_t smem_u32(const void* p) {
    uint32_t a;
    asm("{ .reg .u64 t; cvta.to.shared.u64 t, %1; cvt.u32.u64 %0, t; }" : "=r"(a) : "l"(p));
    return a;
}

#define LDM4(r, a) \
    asm volatile("ldmatrix.sync.aligned.m8n8.x4.shared.b16 {%0,%1,%2,%3}, [%4];" \
        : "=r"((r)[0]), "=r"((r)[1]), "=r"((r)[2]), "=r"((r)[3]) : "r"(a))

#define MMA(d, a, b0, b1) \
    asm volatile("mma.sync.aligned.m16n8k16.row.col.f32.bf16.bf16.f32 " \
        "{%0,%1,%2,%3}, {%4,%5,%6,%7}, {%8,%9}, {%0,%1,%2,%3};" \
        : "+f"((d)[0]), "+f"((d)[1]), "+f"((d)[2]), "+f"((d)[3]) \
        : "r"((a)[0]), "r"((a)[1]), "r"((a)[2]), "r"((a)[3]), "r"(b0), "r"(b1))

// ================= layernorm =================
__global__ void ln_kernel(const float* __restrict__ x, const float* __restrict__ g,
                          const float* __restrict__ bta, float* __restrict__ out) {
    int row = blockIdx.x;
    int tid = threadIdx.x;
    const float4* xr = (const float4*)(x + (size_t)row * DIM);
    float4 v = xr[tid];
    float s  = v.x + v.y + v.z + v.w;
    float ss = v.x * v.x + v.y * v.y + v.z * v.z + v.w * v.w;
    __shared__ float shs[8], shss[8];
    __shared__ float mu_s, rstd_s;
    #pragma unroll
    for (int o = 16; o; o >>= 1) {
        s  += __shfl_down_sync(0xffffffffu, s, o);
        ss += __shfl_down_sync(0xffffffffu, ss, o);
    }
    int w = tid >> 5, lane = tid & 31;
    if (lane == 0) { shs[w] = s; shss[w] = ss; }
    __syncthreads();
    if (tid == 0) {
        float ts = 0.f, tss = 0.f;
        #pragma unroll
        for (int i = 0; i < 8; i++) { ts += shs[i]; tss += shss[i]; }
        float mu = ts * (1.f / DIM);
        float var = tss * (1.f / DIM) - mu * mu;
        mu_s = mu;
        rstd_s = rsqrtf(var + 1e-5f);
    }
    __syncthreads();
    float mu = mu_s, rs = rstd_s;
    float4 g4 = ((const float4*)g)[tid];
    float4 b4 = ((const float4*)bta)[tid];
    float4 r;
    r.x = (v.x - mu) * rs * g4.x + b4.x;
    r.y = (v.y - mu) * rs * g4.y + b4.y;
    r.z = (v.z - mu) * rs * g4.z + b4.z;
    r.w = (v.w - mu) * rs * g4.w + b4.w;
    ((float4*)(out + (size_t)row * DIM))[tid] = r;
}

// ================= tensor-core GEMM NT via mma.sync (templated tiles) =======
// C[M,N] = A[M,K] @ W[N,K]^T, fp32 in/out, bf16 hi/lo split (3 MMA terms)
struct GemmDesc {
    const float* A;
    const float* W;
    const float* bias;   // nullable
    const float* res;    // nullable
    float* C;
    int N;
    int K;
    int epi;             // 0 none, 1 sigmoid
};
struct GemmArgs { GemmDesc d[5]; };

// global -> regs: ROWS x 32 fp32 tile, row stride K
template<int CNT, int NTHR>
__device__ __forceinline__ void ldg_rows(const float* __restrict__ g, int K, int k0,
                                         float4 (&p)[CNT], int tid) {
    #pragma unroll
    for (int i = 0; i < CNT; i++) {
        int idx = tid + i * NTHR;
        int r = idx >> 3, kq = idx & 7;
        p[i] = *(const float4*)(g + (size_t)r * K + k0 + (kq << 2));
    }
}
// regs -> bf16 hi/lo -> padded SMEM (80B row stride)
template<int CNT, int NTHR>
__device__ __forceinline__ void cvt_sts(const float4 (&p)[CNT], char* hi, char* lo, int tid) {
    #pragma unroll
    for (int i = 0; i < CNT; i++) {
        int idx = tid + i * NTHR;
        int r = idx >> 3, kq = idx & 7;
        float4 v = p[i];
        uint32_t u0 = __float_as_uint(v.x), u1 = __float_as_uint(v.y);
        uint32_t u2 = __float_as_uint(v.z), u3 = __float_as_uint(v.w);
        uint32_t h01 = __byte_perm(u0, u1, 0x7632);
        uint32_t h23 = __byte_perm(u2, u3, 0x7632);
        float r0 = v.x - __uint_as_float(u0 & 0xffff0000u);
        float r1 = v.y - __uint_as_float(u1 & 0xffff0000u);
        float r2 = v.z - __uint_as_float(u2 & 0xffff0000u);
        float r3 = v.w - __uint_as_float(u3 & 0xffff0000u);
        uint32_t l01, l23;
        asm("cvt.rn.bf16x2.f32 %0, %1, %2;" : "=r"(l01) : "f"(r1), "f"(r0));
        asm("cvt.rn.bf16x2.f32 %0, %1, %2;" : "=r"(l23) : "f"(r3), "f"(r2));
        int off = r * 80 + kq * 8;
        *(uint2*)(hi + off) = make_uint2(h01, h23);
        *(uint2*)(lo + off) = make_uint2(l01, l23);
    }
}

template<int TM, int TN, int NTHR>
__global__ __launch_bounds__(NTHR, (NTHR == 128) ? 2 : 1) void gemm_mma(GemmArgs args) {
    extern __shared__ char smem[];
    constexpr int MATA = TM * 80;
    constexpr int MATW = TN * 80;
    constexpr int STG = 2 * (MATA + MATW);
    constexpr int CA = TM * 8 / NTHR;
    constexpr int CW = TN * 8 / NTHR;
    constexpr int MW = TM / 32;

    const GemmDesc dd = args.d[blockIdx.z];
    const int N = dd.N, K = dd.K;
    const int bn0 = blockIdx.x * TN;
    const int bm0 = blockIdx.y * TM;
    if (bn0 >= N) return;

    const int tid = threadIdx.x;
    const int wid = tid >> 5, lane = tid & 31;
    const int m0 = (wid % MW) * 32;
    const int n0 = (wid / MW) * 32;
    const int grp = lane >> 3, lrow = lane & 7;
    const uint32_t sbase = smem_u32(smem);

    const float* Ag = dd.A + (size_t)bm0 * K;
    const float* Wg = dd.W + (size_t)bn0 * K;

    uint32_t aoff[2], boff[2];
    #pragma unroll
    for (int mi = 0; mi < 2; mi++)
        aoff[mi] = (uint32_t)((m0 + mi * 16 + (grp & 1) * 8 + lrow) * 80 + (grp >> 1) * 16);
    #pragma unroll
    for (int bi = 0; bi < 2; bi++)
        boff[bi] = (uint32_t)((n0 + bi * 16 + (grp >> 1) * 8 + lrow) * 80 + (grp & 1) * 16);

    float acc[2][4][4];
    #pragma unroll
    for (int mi = 0; mi < 2; mi++)
        #pragma unroll
        for (int ni = 0; ni < 4; ni++)
            acc[mi][ni][0] = acc[mi][ni][1] = acc[mi][ni][2] = acc[mi][ni][3] = 0.f;

    const int nk = K >> 5;
    // prologue: fill stage 0
    {
        float4 pA[CA], pW[CW];
        ldg_rows<CA, NTHR>(Ag, K, 0, pA, tid);
        ldg_rows<CW, NTHR>(Wg, K, 0, pW, tid);
        cvt_sts<CA, NTHR>(pA, smem, smem + MATA, tid);
        cvt_sts<CW, NTHR>(pW, smem + 2 * MATA, smem + 2 * MATA + MATW, tid);
    }
    __syncthreads();

    for (int it = 0; it < nk; it++) {
        float4 pA[CA], pW[CW];
        if (it + 1 < nk) {
            ldg_rows<CA, NTHR>(Ag, K, (it + 1) << 5, pA, tid);
            ldg_rows<CW, NTHR>(Wg, K, (it + 1) << 5, pW, tid);
        }
        const uint32_t sA  = sbase + (it & 1) * STG;
        const uint32_t sAl = sA + MATA, sWh = sA + 2 * MATA, sWl = sA + 2 * MATA + MATW;
        #pragma unroll
        for (int ks = 0; ks < 2; ks++) {
            const uint32_t kb = ks * 32;
            uint32_t Ah[2][4], Al[2][4], Bh[4][2], Bl[4][2];
            #pragma unroll
            for (int mi = 0; mi < 2; mi++) {
                LDM4(Ah[mi], sA  + aoff[mi] + kb);
                LDM4(Al[mi], sAl + aoff[mi] + kb);
            }
            #pragma unroll
            for (int bi = 0; bi < 2; bi++) {
                uint32_t t[4];
                LDM4(t, sWh + boff[bi] + kb);
                Bh[2 * bi][0] = t[0]; Bh[2 * bi][1] = t[1];
                Bh[2 * bi + 1][0] = t[2]; Bh[2 * bi + 1][1] = t[3];
                LDM4(t, sWl + boff[bi] + kb);
                Bl[2 * bi][0] = t[0]; Bl[2 * bi][1] = t[1];
                Bl[2 * bi + 1][0] = t[2]; Bl[2 * bi + 1][1] = t[3];
            }
            #pragma unroll
            for (int mi = 0; mi < 2; mi++)
                #pragma unroll
                for (int ni = 0; ni < 4; ni++) {
                    MMA(acc[mi][ni], Ah[mi], Bh[ni][0], Bh[ni][1]);
                    MMA(acc[mi][ni], Ah[mi], Bl[ni][0], Bl[ni][1]);
                    MMA(acc[mi][ni], Al[mi], Bh[ni][0], Bh[ni][1]);
                }
        }
        if (it + 1 < nk) {
            char* st = smem + ((it + 1) & 1) * STG;
            cvt_sts<CA, NTHR>(pA, st, st + MATA, tid);
            cvt_sts<CW, NTHR>(pW, st + 2 * MATA, st + 2 * MATA + MATW, tid);
        }
        __syncthreads();
    }

    // epilogue
    const int qrow = lane >> 2, qcol = (lane & 3) * 2;
    #pragma unroll
    for (int ni = 0; ni < 4; ni++) {
        const int c = bn0 + n0 + ni * 8 + qcol;
        float2 bb = make_float2(0.f, 0.f);
        if (dd.bias) bb = *(const float2*)(dd.bias + c);
        #pragma unroll
        for (int mi = 0; mi < 2; mi++) {
            const int r = bm0 + m0 + mi * 16 + qrow;
            float v0 = acc[mi][ni][0] + bb.x;
            float v1 = acc[mi][ni][1] + bb.y;
            float v2 = acc[mi][ni][2] + bb.x;
            float v3 = acc[mi][ni][3] + bb.y;
            if (dd.epi == 1) {
                v0 = 1.f / (1.f + expf(-v0)); v1 = 1.f / (1.f + expf(-v1));
                v2 = 1.f / (1.f + expf(-v2)); v3 = 1.f / (1.f + expf(-v3));
            }
            if (dd.res) {
                float2 r0 = *(const float2*)(dd.res + (size_t)r * N + c);
                float2 r1 = *(const float2*)(dd.res + (size_t)(r + 8) * N + c);
                v0 += r0.x; v1 += r0.y; v2 += r1.x; v3 += r1.y;
            }
            *(float2*)(dd.C + (size_t)r * N + c) = make_float2(v0, v1);
            *(float2*)(dd.C + (size_t)(r + 8) * N + c) = make_float2(v2, v3);
        }
    }
}

#define SMEM_A (2 * 2 * (64 * 80 + 128 * 80))  // <64,128>: 61440
#define SMEM_B (2 * 2 * (64 * 80 + 64 * 80))   // <64,64>:  40960

// ================= causal conv (k=4) + silu =================
__global__ void conv_silu_kernel(const float* __restrict__ xt, const float* __restrict__ w,
                                 const float* __restrict__ cb, float* __restrict__ xc) {
    int b = blockIdx.y;
    int p = blockIdx.x * 256 + threadIdx.x;
    const float* xr = xt + (size_t)b * P;
    float acc = cb[0];
    #pragma unroll
    for (int j = 0; j < KER; j++) {
        int idx = p - (KER - 1) + j;
        if (idx >= 0) acc += w[j] * xr[idx];
    }
    float s = 1.f / (1.f + expf(-acc));
    xc[(size_t)b * P + p] = acc * s;
}

// ================= i/f gates: one block per (b,h) =================
__global__ __launch_bounds__(128) void if_kernel(
        const float* __restrict__ xc,
        const float* __restrict__ Wi, const float* __restrict__ bi,
        const float* __restrict__ Wf, const float* __restrict__ bfb,
        const float* __restrict__ m_tm1, float* __restrict__ m_out,
        float* __restrict__ ie, float* __restrict__ fe) {
    int bh = blockIdx.x;
    int b = bh >> 3, h = bh & 7;
    int tid = threadIdx.x;
    const float* x  = xc + (size_t)b * P;
    const float* wi = Wi + (size_t)h * P;
    const float* wf = Wf + (size_t)h * P;
    float ai = 0.f, af = 0.f;
    #pragma unroll
    for (int k = tid * 4; k < P; k += 512) {
        float4 xv  = *(const float4*)(x + k);
        float4 wiv = *(const float4*)(wi + k);
        float4 wfv = *(const float4*)(wf + k);
        ai += xv.x * wiv.x + xv.y * wiv.y + xv.z * wiv.z + xv.w * wiv.w;
        af += xv.x * wfv.x + xv.y * wfv.y + xv.z * wfv.z + xv.w * wfv.w;
    }
    __shared__ float si[4], sf[4];
    #pragma unroll
    for (int o = 16; o; o >>= 1) {
        ai += __shfl_down_sync(0xffffffffu, ai, o);
        af += __shfl_down_sync(0xffffffffu, af, o);
    }
    int w = tid >> 5, lane = tid & 31;
    if (lane == 0) { si[w] = ai; sf[w] = af; }
    __syncthreads();
    if (tid == 0) {
        float i_t = si[0] + si[1] + si[2] + si[3] + bi[h];
        float f_t = sf[0] + sf[1] + sf[2] + sf[3] + bfb[h];
        float mp = m_tm1[bh];
        float m = fmaxf(f_t + mp, i_t);
        m_out[bh] = m;
        ie[bh] = expf(i_t - m);
        fe[bh] = expf(f_t - m + mp);
    }
}

// ================= fused state update + readout + groupnorm + gating ========
__global__ __launch_bounds__(128) void state_kernel(
    const float* __restrict__ c_tm1, const float* __restrict__ n_tm1,
    const float* __restrict__ q, const float* __restrict__ k, const float* __restrict__ v,
    const float* __restrict__ o, const float* __restrict__ ie_, const float* __restrict__ fe_,
    const float* __restrict__ skip, const float* __restrict__ r,
    const float* __restrict__ gn_g, const float* __restrict__ gn_b,
    float* __restrict__ c_out, float* __restrict__ n_out, float* __restrict__ y) {
    int bh = blockIdx.x;
    int b = bh >> 3, h = bh & 7;
    __shared__ float qs[D], ks[D], vs[D], hnum[D];
    __shared__ float red[4], rs1[4], rs2[4];
    int tid = threadIdx.x;
    int base = b * HD + h * D;
    qs[tid] = q[base + tid];
    ks[tid] = k[base + tid] * 0.08838834764831845f;   // 1/sqrt(128)
    vs[tid] = v[base + tid];
    float ie = ie_[bh], fe = fe_[bh];
    __syncthreads();

    const float4* crow = (const float4*)(c_tm1 + (size_t)bh * D * D);
    float4* cout = (float4*)(c_out + (size_t)bh * D * D);
    int w = tid >> 5, lane = tid & 31;
    float4 k4 = ((const float4*)ks)[lane];
    float4 q4 = ((const float4*)qs)[lane];
    #pragma unroll 4
    for (int it = 0; it < 32; it++) {
        int d = it * 4 + w;
        float4 c4 = crow[d * 32 + lane];
        float ivd = ie * vs[d];
        float4 cn;
        cn.x = fe * c4.x + ivd * k4.x;
        cn.y = fe * c4.y + ivd * k4.y;
        cn.z = fe * c4.z + ivd * k4.z;
        cn.w = fe * c4.w + ivd * k4.w;
        cout[d * 32 + lane] = cn;
        float part = cn.x * q4.x + cn.y * q4.y + cn.z * q4.z + cn.w * q4.w;
        #pragma unroll
        for (int off = 16; off; off >>= 1) part += __shfl_down_sync(0xffffffffu, part, off);
        if (lane == 0) hnum[d] = part;
    }
    __syncthreads();

    int d = tid;
    float nv = fe * n_tm1[bh * D + d] + ie * ks[d];
    n_out[bh * D + d] = nv;
    float dn = nv * qs[d];
    #pragma unroll
    for (int off = 16; off; off >>= 1) dn += __shfl_down_sync(0xffffffffu, dn, off);
    if (lane == 0) red[w] = dn;
    __syncthreads();
    float denom = fmaxf(red[0] + red[1] + red[2] + red[3], 1.0f);
    float ht = o[base + d] * hnum[d] / denom;

    float s1 = ht, s2 = ht * ht;
    #pragma unroll
    for (int off = 16; off; off >>= 1) {
        s1 += __shfl_down_sync(0xffffffffu, s1, off);
        s2 += __shfl_down_sync(0xffffffffu, s2, off);
    }
    if (lane == 0) { rs1[w] = s1; rs2[w] = s2; }
    __syncthreads();
    float mu  = (rs1[0] + rs1[1] + rs1[2] + rs1[3]) * (1.f / D);
    float var = (rs2[0] + rs2[1] + rs2[2] + rs2[3]) * (1.f / D) - mu * mu;
    float rstd = rsqrtf(var + 1e-5f);
    float xn = (ht - mu) * rstd * gn_g[h * D + d] + gn_b[h * D + d];
    float rv = r[base + d];
    float yv = (xn + skip[base + d]) * (rv / (1.f + expf(-rv)));
    y[base + d] = yv;
}

// ---------------------------------------------------------------------------
extern "C" void kernel_launch(void* const* d_in, const int* in_sizes, int n_in,
                              void* d_out, int out_size) {
    const float* seq    = (const float*)d_in[0];
    const float* c_tm1  = (const float*)d_in[1];
    const float* n_tm1  = (const float*)d_in[2];
    const float* m_tm1  = (const float*)d_in[3];
    const float* ln_g   = (const float*)d_in[4];
    const float* ln_b   = (const float*)d_in[5];
    const float* Wul    = (const float*)d_in[6];
    const float* bul    = (const float*)d_in[7];
    const float* Wur    = (const float*)d_in[8];
    const float* bur    = (const float*)d_in[9];
    const float* conv_w = (const float*)d_in[10];
    const float* conv_b = (const float*)d_in[11];
    const float* Wskip  = (const float*)d_in[12];
    const float* Wi     = (const float*)d_in[13];
    const float* bi     = (const float*)d_in[14];
    const float* Wf     = (const float*)d_in[15];
    const float* bf     = (const float*)d_in[16];
    const float* Wo     = (const float*)d_in[17];
    const float* bo     = (const float*)d_in[18];
    const float* Wq     = (const float*)d_in[19];
    const float* bq     = (const float*)d_in[20];
    const float* Wk     = (const float*)d_in[21];
    const float* bk     = (const float*)d_in[22];
    const float* Wv     = (const float*)d_in[23];
    const float* bv     = (const float*)d_in[24];
    const float* gn_g   = (const float*)d_in[25];
    const float* gn_b   = (const float*)d_in[26];
    const float* Wd     = (const float*)d_in[27];
    const float* bd     = (const float*)d_in[28];

    float* out   = (float*)d_out;
    float* c_out = out + (size_t)B * DIM;
    float* n_out = c_out + (size_t)B * H * D * D;
    float* m_out = n_out + (size_t)B * H * D;

    float *xn, *xt, *xc, *rt, *qq, *kk, *vv, *oo, *sk, *iee, *fee, *yy;
    cudaGetSymbolAddress((void**)&xn,  g_xn);
    cudaGetSymbolAddress((void**)&xt,  g_xt);
    cudaGetSymbolAddress((void**)&xc,  g_xc);
    cudaGetSymbolAddress((void**)&rt,  g_rt);
    cudaGetSymbolAddress((void**)&qq,  g_q);
    cudaGetSymbolAddress((void**)&kk,  g_k);
    cudaGetSymbolAddress((void**)&vv,  g_v);
    cudaGetSymbolAddress((void**)&oo,  g_o);
    cudaGetSymbolAddress((void**)&sk,  g_sk);
    cudaGetSymbolAddress((void**)&iee, g_ie);
    cudaGetSymbolAddress((void**)&fee, g_fe);
    cudaGetSymbolAddress((void**)&yy,  g_y);

    cudaFuncSetAttribute(gemm_mma<64, 128, 256>,
                         cudaFuncAttributeMaxDynamicSharedMemorySize, SMEM_A);
    cudaFuncSetAttribute(gemm_mma<64, 64, 128>,
                         cudaFuncAttributeMaxDynamicSharedMemorySize, SMEM_B);

    // 1. layernorm
    ln_kernel<<<B, 256>>>(seq, ln_g, ln_b, xn);

    // 2+3. x_t = xn@Wul^T+bul [B,P] and r_t = xn@Wur^T+bur [B,HD]
    {
        GemmArgs a{};
        a.d[0] = {xn, Wul, bul, nullptr, xt, P,  DIM, 0};
        a.d[1] = {xn, Wur, bur, nullptr, rt, HD, DIM, 0};
        gemm_mma<64, 128, 256><<<dim3(P / 128, B / 64, 2), 256, SMEM_A>>>(a);
    }

    // 4. causal conv + silu -> x_c
    conv_silu_kernel<<<dim3(P / 256, B), 256>>>(xt, conv_w, conv_b, xc);

    // 5. gates i,f + m_t + exp factors (one block per (b,h))
    if_kernel<<<B * H, 128>>>(xc, Wi, bi, Wf, bf, m_tm1, m_out, iee, fee);

    // 6. batched 5x GEMM (N=1024, K=2048), 64x64 tiles -> 320 CTAs
    {
        GemmArgs a{};
        a.d[0] = {xc, Wq,    bq,      nullptr, qq, HD, P, 0};
        a.d[1] = {xc, Wk,    bk,      nullptr, kk, HD, P, 0};
        a.d[2] = {xt, Wv,    bv,      nullptr, vv, HD, P, 0};
        a.d[3] = {xt, Wo,    bo,      nullptr, oo, HD, P, 1};   // sigmoid
        a.d[4] = {xc, Wskip, nullptr, nullptr, sk, HD, P, 0};
        gemm_mma<64, 64, 128><<<dim3(HD / 64, B / 64, 5), 128, SMEM_B>>>(a);
    }

    // 7. fused state update + readout + groupnorm + skip + silu(r) gate
    state_kernel<<<B * H, 128>>>(c_tm1, n_tm1, qq, kk, vv, oo, iee, fee,
                                 sk, rt, gn_g, gn_b, c_out, n_out, yy);

    // 8. out = y @ Wd^T + bd + seq, 64x64 tiles -> 64 CTAs
    {
        GemmArgs a{};
        a.d[0] = {yy, Wd, bd, seq, out, DIM, HD, 0};
        gemm_mma<64, 64, 128><<<dim3(DIM / 64, B / 64, 1), 128, SMEM_B>>>(a);
    }
}